// round 6
// baseline (speedup 1.0000x reference)
#include <cuda_runtime.h>

// GATLayer: B=8, N=1024, INP=7, D=32, H=4
// Identity: softmax_j(s_i + s_j + ba) == softmax_j(s_j) (s_i, ba constant in j)
// => attention weights independent of i => output row constant per batch.

#define BB 8
#define NN 1024
#define DD 32
#define HH 4

__device__ float4 g_fx4[BB * NN * 8];        // fx [8192][32] as float4[8192][8]
__device__ float4 g_s4[BB * NN];             // s_j [8192][4]
__device__ __align__(16) float g_o[BB * DD]; // per-batch output row [8][32]

static __device__ __forceinline__ float lrelu(float t) {
    return fmaxf(t, 0.2f * t);
}

// ---------------------------------------------------------------------------
// Kernel 1: message MLP + s_j.
// 256 blocks x 256 threads; 32 nodes/block, 8 threads per node (s = t&7).
//  Stage A (L1): lane s computes h1 units [8s,8s+8)  -> smem sh1
//  Stage B (L2): lane s computes h2 units [8s,8s+8)  -> smem sh2
//  Stage C (L3): lane s computes fx dims  [4s,4s+4)  -> direct float4 store
// Cross-lane values exchanged via smem between stage barriers (NO shfl in
// inner loops). sh1/sh2 row stride = 68 floats so the per-k scalar broadcast
// read hits 4 distinct banks across the warp's 4 node groups.
// W1/W2 float4 reads use a per-half rotation (lanes 4-7 swap their two
// float4s) so the 8 lanes of a group cover all 32 banks conflict-free.
// ---------------------------------------------------------------------------
#define HSTR 68

__global__ __launch_bounds__(256) void k_mlp(
    const float* __restrict__ x,
    const float* __restrict__ W1, const float* __restrict__ b1,
    const float* __restrict__ W2, const float* __restrict__ b2,
    const float* __restrict__ W3, const float* __restrict__ b3,
    const float* __restrict__ Wa)
{
    __shared__ float sW1[7 * 64];
    __shared__ float sW2[64 * 64];
    __shared__ float sW3[64 * 32];
    __shared__ float sWaj[32 * 4];       // Wa rows 32..63, [d][h]
    __shared__ float sb1[64], sb2[64], sb3[32];
    __shared__ float sx[224];            // x for this block's 32 nodes
    __shared__ float sh1[32 * HSTR];     // h1 scratch (bank-skewed rows)
    __shared__ float sh2[32 * HSTR];     // h2 scratch

    const int t = threadIdx.x;

    // ---- stage weights + x (float4 where possible) ----
    {
        float4* d2 = (float4*)sW2; const float4* s2 = (const float4*)W2;
#pragma unroll
        for (int i = 0; i < 4; i++) d2[t + i * 256] = s2[t + i * 256];
        float4* d3 = (float4*)sW3; const float4* s3 = (const float4*)W3;
#pragma unroll
        for (int i = 0; i < 2; i++) d3[t + i * 256] = s3[t + i * 256];
        if (t < 112) ((float4*)sW1)[t] = ((const float4*)W1)[t];
        else if (t < 144) ((float4*)sWaj)[t - 112] = ((const float4*)(Wa + 128))[t - 112];
        else if (t < 160) ((float4*)sb1)[t - 144] = ((const float4*)b1)[t - 144];
        else if (t < 176) ((float4*)sb2)[t - 160] = ((const float4*)b2)[t - 160];
        else if (t < 184) ((float4*)sb3)[t - 176] = ((const float4*)b3)[t - 176];
        if (t < 224) sx[t] = __ldg(x + blockIdx.x * 224 + t);
    }
    __syncthreads();

    const int nl = t >> 3;               // node local 0..31
    const int node = blockIdx.x * 32 + nl;
    const int s = t & 7;
    const int rot = s >> 2;              // 0/1: swap the two float4 reads

    // ---- Stage A: layer 1, units [8s, 8s+8) ----
    {
        float xv[7];
#pragma unroll
        for (int k = 0; k < 7; k++) xv[k] = sx[nl * 7 + k];

        float h1[8];
#pragma unroll
        for (int c = 0; c < 2; c++) {
            const int cc = (c + rot) & 1;
            const float4 b = ((const float4*)sb1)[2 * s + cc];
            h1[cc * 4 + 0] = b.x; h1[cc * 4 + 1] = b.y;
            h1[cc * 4 + 2] = b.z; h1[cc * 4 + 3] = b.w;
        }
#pragma unroll
        for (int k = 0; k < 7; k++) {
            const float xk = xv[k];
            const float4* row = (const float4*)(sW1 + k * 64);
#pragma unroll
            for (int c = 0; c < 2; c++) {
                const int cc = (c + rot) & 1;
                const float4 w = row[2 * s + cc];
                h1[cc * 4 + 0] += xk * w.x;
                h1[cc * 4 + 1] += xk * w.y;
                h1[cc * 4 + 2] += xk * w.z;
                h1[cc * 4 + 3] += xk * w.w;
            }
        }
        float4* o = (float4*)(sh1 + nl * HSTR + 8 * s);
        o[0] = make_float4(lrelu(h1[0]), lrelu(h1[1]), lrelu(h1[2]), lrelu(h1[3]));
        o[1] = make_float4(lrelu(h1[4]), lrelu(h1[5]), lrelu(h1[6]), lrelu(h1[7]));
    }
    __syncthreads();

    // ---- Stage B: layer 2, units [8s, 8s+8) ----
    {
        float a8[8];
#pragma unroll
        for (int c = 0; c < 2; c++) {
            const int cc = (c + rot) & 1;
            const float4 b = ((const float4*)sb2)[2 * s + cc];
            a8[cc * 4 + 0] = b.x; a8[cc * 4 + 1] = b.y;
            a8[cc * 4 + 2] = b.z; a8[cc * 4 + 3] = b.w;
        }
        const float* h1r = sh1 + nl * HSTR;
#pragma unroll
        for (int k = 0; k < 64; k++) {
            const float hk = h1r[k];                 // broadcast within group
            const float4* row = (const float4*)(sW2 + k * 64);
#pragma unroll
            for (int c = 0; c < 2; c++) {
                const int cc = (c + rot) & 1;
                const float4 w = row[2 * s + cc];
                a8[cc * 4 + 0] += hk * w.x;
                a8[cc * 4 + 1] += hk * w.y;
                a8[cc * 4 + 2] += hk * w.z;
                a8[cc * 4 + 3] += hk * w.w;
            }
        }
        float4* o = (float4*)(sh2 + nl * HSTR + 8 * s);
        o[0] = make_float4(lrelu(a8[0]), lrelu(a8[1]), lrelu(a8[2]), lrelu(a8[3]));
        o[1] = make_float4(lrelu(a8[4]), lrelu(a8[5]), lrelu(a8[6]), lrelu(a8[7]));
    }
    __syncthreads();

    // ---- Stage C: layer 3, dims [4s, 4s+4); even/odd accumulator pairs ----
    float f0, f1, f2, f3;
    {
        const float4 b3v = ((const float4*)sb3)[s];
        float e0 = b3v.x, e1 = b3v.y, e2 = b3v.z, e3 = b3v.w;
        float o0 = 0.f, o1 = 0.f, o2 = 0.f, o3 = 0.f;
        const float* h2r = sh2 + nl * HSTR;
#pragma unroll
        for (int j = 0; j < 64; j += 2) {
            const float hj0 = h2r[j];
            const float hj1 = h2r[j + 1];
            const float4 w0 = ((const float4*)sW3)[j * 8 + s];
            const float4 w1 = ((const float4*)sW3)[(j + 1) * 8 + s];
            e0 += hj0 * w0.x; e1 += hj0 * w0.y; e2 += hj0 * w0.z; e3 += hj0 * w0.w;
            o0 += hj1 * w1.x; o1 += hj1 * w1.y; o2 += hj1 * w1.z; o3 += hj1 * w1.w;
        }
        f0 = e0 + o0; f1 = e1 + o1; f2 = e2 + o2; f3 = e3 + o3;
    }
    g_fx4[node * 8 + s] = make_float4(f0, f1, f2, f3);

    // ---- s_j = fx @ Wa[D:]: partial over this lane's 4 dims, 8-lane reduce
    float sj0, sj1, sj2, sj3;
    {
        const float4 w0 = ((const float4*)sWaj)[4 * s + 0];
        const float4 w1 = ((const float4*)sWaj)[4 * s + 1];
        const float4 w2 = ((const float4*)sWaj)[4 * s + 2];
        const float4 w3 = ((const float4*)sWaj)[4 * s + 3];
        sj0 = f0 * w0.x + f1 * w1.x + f2 * w2.x + f3 * w3.x;
        sj1 = f0 * w0.y + f1 * w1.y + f2 * w2.y + f3 * w3.y;
        sj2 = f0 * w0.z + f1 * w1.z + f2 * w2.z + f3 * w3.z;
        sj3 = f0 * w0.w + f1 * w1.w + f2 * w2.w + f3 * w3.w;
    }
#pragma unroll
    for (int o = 1; o < 8; o <<= 1) {
        sj0 += __shfl_xor_sync(0xffffffffu, sj0, o);
        sj1 += __shfl_xor_sync(0xffffffffu, sj1, o);
        sj2 += __shfl_xor_sync(0xffffffffu, sj2, o);
        sj3 += __shfl_xor_sync(0xffffffffu, sj3, o);
    }
    if (s == 0) g_s4[node] = make_float4(sj0, sj1, sj2, sj3);
}

// ---------------------------------------------------------------------------
// Kernel 2: per-batch softmax over j, aggregation m[h][d] (fx tiled through
// shared), projection. 8 blocks x 256 threads.
// ---------------------------------------------------------------------------
__global__ __launch_bounds__(256) void k_att(
    const float* __restrict__ Ws, const float* __restrict__ bs)
{
    const int b = blockIdx.x;
    const int t = threadIdx.x;
    const int w = t >> 5, lane = t & 31;

    __shared__ float ps[4 * 1024];   // exp(s - max), [h][j]
    __shared__ float4 sfx4[256 * 8]; // 256-row fx tile (32 KB)
    __shared__ float red[4 * 8];
    __shared__ float part[256];
    __shared__ float sm[128];
    __shared__ float pr2[128];

    // ---- load s, per-head max ----
    float sv[4][4];
    float lmax[4] = { -1e30f, -1e30f, -1e30f, -1e30f };
#pragma unroll
    for (int jj = 0; jj < 4; jj++) {
        const float4 v = g_s4[b * 1024 + jj * 256 + t];
        sv[jj][0] = v.x; sv[jj][1] = v.y; sv[jj][2] = v.z; sv[jj][3] = v.w;
        lmax[0] = fmaxf(lmax[0], v.x); lmax[1] = fmaxf(lmax[1], v.y);
        lmax[2] = fmaxf(lmax[2], v.z); lmax[3] = fmaxf(lmax[3], v.w);
    }
#pragma unroll
    for (int o = 16; o > 0; o >>= 1)
#pragma unroll
        for (int h = 0; h < 4; h++)
            lmax[h] = fmaxf(lmax[h], __shfl_xor_sync(0xffffffffu, lmax[h], o));
    if (lane == 0)
#pragma unroll
        for (int h = 0; h < 4; h++) red[h * 8 + w] = lmax[h];
    __syncthreads();
    float mx[4];
#pragma unroll
    for (int h = 0; h < 4; h++) {
        float m = red[h * 8];
#pragma unroll
        for (int ww = 1; ww < 8; ww++) m = fmaxf(m, red[h * 8 + ww]);
        mx[h] = m;
    }
    __syncthreads();

    // ---- exp + per-head sum ----
    float lsum[4] = { 0.f, 0.f, 0.f, 0.f };
#pragma unroll
    for (int jj = 0; jj < 4; jj++) {
        const int j = jj * 256 + t;
#pragma unroll
        for (int h = 0; h < 4; h++) {
            const float e = __expf(sv[jj][h] - mx[h]);
            ps[h * 1024 + j] = e;
            lsum[h] += e;
        }
    }
#pragma unroll
    for (int o = 16; o > 0; o >>= 1)
#pragma unroll
        for (int h = 0; h < 4; h++)
            lsum[h] += __shfl_xor_sync(0xffffffffu, lsum[h], o);
    if (lane == 0)
#pragma unroll
        for (int h = 0; h < 4; h++) red[h * 8 + w] = lsum[h];
    __syncthreads();
    float sums[4];
#pragma unroll
    for (int h = 0; h < 4; h++) {
        float s = red[h * 8];
#pragma unroll
        for (int ww = 1; ww < 8; ww++) s += red[h * 8 + ww];
        sums[h] = s;
    }

    // ---- aggregation: m[h][d] = sum_j p[h][j]*fx[j][d], fx tiled via smem.
    const int o = t & 127, half = t >> 7;
    const int h = o >> 5, d = o & 31;
    float a0 = 0.f, a1 = 0.f, a2 = 0.f, a3 = 0.f;
#pragma unroll 1
    for (int tile = 0; tile < 4; tile++) {
        __syncthreads();
        const float4* src = g_fx4 + (b * 1024 + tile * 256) * 8;
        for (int i = t; i < 2048; i += 256) sfx4[i] = src[i];
        __syncthreads();
        const float* pr  = ps + h * 1024 + tile * 256 + half * 128;
        const float* fxp = (const float*)sfx4 + half * 128 * 32 + d;
#pragma unroll 8
        for (int jj = 0; jj < 128; jj += 4) {
            a0 += pr[jj + 0] * fxp[(jj + 0) * 32];
            a1 += pr[jj + 1] * fxp[(jj + 1) * 32];
            a2 += pr[jj + 2] * fxp[(jj + 2) * 32];
            a3 += pr[jj + 3] * fxp[(jj + 3) * 32];
        }
    }
    part[t] = (a0 + a1) + (a2 + a3);
    __syncthreads();
    if (t < 128) sm[t] = (part[t] + part[t + 128]) / sums[h];
    __syncthreads();

    // ---- projection
    if (t < 128) {
        const int kg = t >> 5, dd = t & 31;
        float a = 0.f;
#pragma unroll
        for (int kk = 0; kk < 32; kk++) {
            const int k = kg * 32 + kk;
            a += sm[k] * Ws[k * 32 + dd];
        }
        pr2[t] = a;
    }
    __syncthreads();
    if (t < 32)
        g_o[b * 32 + t] = bs[t] + ((pr2[t] + pr2[t + 32]) + (pr2[t + 64] + pr2[t + 96]));
}

// ---------------------------------------------------------------------------
// Kernel 3: broadcast per-batch rows to the full [B,N,D] output.
// ---------------------------------------------------------------------------
__global__ __launch_bounds__(256) void k_bcast(float4* __restrict__ out)
{
    const int g = blockIdx.x * 256 + threadIdx.x; // float4 index
    const int b = g >> 13;                        // 8192 float4 per batch
    const int d4 = g & 7;
    out[g] = *(const float4*)(g_o + b * 32 + d4 * 4);
}

extern "C" void kernel_launch(void* const* d_in, const int* in_sizes, int n_in,
                              void* d_out, int out_size)
{
    const float* x  = (const float*)d_in[0];
    const float* W1 = (const float*)d_in[1];
    const float* b1 = (const float*)d_in[2];
    const float* W2 = (const float*)d_in[3];
    const float* b2 = (const float*)d_in[4];
    const float* W3 = (const float*)d_in[5];
    const float* b3 = (const float*)d_in[6];
    const float* Wa = (const float*)d_in[7];
    // d_in[8] = ba: cancels in the softmax
    const float* Ws = (const float*)d_in[9];
    const float* bs = (const float*)d_in[10];

    k_mlp<<<256, 256>>>(x, W1, b1, W2, b2, W3, b3, Wa);
    k_att<<<8, 256>>>(Ws, bs);
    k_bcast<<<256, 256>>>((float4*)d_out);
}

// round 7
// speedup vs baseline: 2.8327x; 2.8327x over previous
#include <cuda_runtime.h>

// GATLayer: B=8, N=1024, INP=7, D=32, H=4
// Identity: softmax_j(s_i + s_j + ba) == softmax_j(s_j) (s_i, ba constant in j)
// => attention weights independent of i => output row constant per batch.

#define BB 8
#define NN 1024
#define DD 32
#define HH 4

__device__ float4 g_fx4[BB * NN * 8];        // fx [8192][32] as float4[8192][8]
__device__ float4 g_s4[BB * NN];             // s_j [8192][4]
__device__ __align__(16) float g_o[BB * DD]; // per-batch output row [8][32]

static __device__ __forceinline__ float lrelu(float t) {
    return fmaxf(t, 0.2f * t);
}

// ---------------------------------------------------------------------------
// Kernel 1: message MLP + s_j.
// 256 blocks x 256 threads; 32 nodes/block, 8 threads per node (s = t&7).
//  Stage A (L1): lane s computes h1 units [8s,8s+8)  -> smem sh1
//  Stage B (L2): lane s computes h2 units [8s,8s+8)  -> smem sh2
//  Stage C (L3): lane s computes fx dims  [4s,4s+4)  -> direct float4 store
// Cross-lane exchange via smem between stage barriers. sh1/sh2 row stride =
// 68 floats (scalar broadcast read hits 4 distinct banks across the warp's
// 4 node groups). The two weight float4 reads per row are bank-rotated across
// lane halves; the rotation lives ONLY in addresses — accumulators are
// explicit scalars bound to fixed column groups (A <-> 2s+rot, B <-> 2s+1-rot)
// so nothing spills to local memory.
// ---------------------------------------------------------------------------
#define HSTR 68

__global__ __launch_bounds__(256) void k_mlp(
    const float* __restrict__ x,
    const float* __restrict__ W1, const float* __restrict__ b1,
    const float* __restrict__ W2, const float* __restrict__ b2,
    const float* __restrict__ W3, const float* __restrict__ b3,
    const float* __restrict__ Wa)
{
    __shared__ float sW1[7 * 64];
    __shared__ float sW2[64 * 64];
    __shared__ float sW3[64 * 32];
    __shared__ float sWaj[32 * 4];       // Wa rows 32..63, [d][h]
    __shared__ float sb1[64], sb2[64], sb3[32];
    __shared__ float sx[224];            // x for this block's 32 nodes
    __shared__ float sh1[32 * HSTR];     // h1 scratch (bank-skewed rows)
    __shared__ float sh2[32 * HSTR];     // h2 scratch

    const int t = threadIdx.x;

    // ---- stage weights + x ----
    {
        float4* d2 = (float4*)sW2; const float4* s2 = (const float4*)W2;
#pragma unroll
        for (int i = 0; i < 4; i++) d2[t + i * 256] = s2[t + i * 256];
        float4* d3 = (float4*)sW3; const float4* s3 = (const float4*)W3;
#pragma unroll
        for (int i = 0; i < 2; i++) d3[t + i * 256] = s3[t + i * 256];
        if (t < 112) ((float4*)sW1)[t] = ((const float4*)W1)[t];
        else if (t < 144) ((float4*)sWaj)[t - 112] = ((const float4*)(Wa + 128))[t - 112];
        else if (t < 160) ((float4*)sb1)[t - 144] = ((const float4*)b1)[t - 144];
        else if (t < 176) ((float4*)sb2)[t - 160] = ((const float4*)b2)[t - 160];
        else if (t < 184) ((float4*)sb3)[t - 176] = ((const float4*)b3)[t - 176];
        if (t < 224) sx[t] = __ldg(x + blockIdx.x * 224 + t);
    }
    __syncthreads();

    const int nl = t >> 3;               // node local 0..31
    const int node = blockIdx.x * 32 + nl;
    const int s = t & 7;
    const int rot = s >> 2;              // 0/1
    const int cgA = 2 * s + rot;         // accumulator A's column group (float4 idx)
    const int cgB = 2 * s + 1 - rot;     // accumulator B's column group

    // ---- Stage A: layer 1 ----
    {
        float xv[7];
#pragma unroll
        for (int k = 0; k < 7; k++) xv[k] = sx[nl * 7 + k];

        const float4 bA = ((const float4*)sb1)[cgA];
        const float4 bB = ((const float4*)sb1)[cgB];
        float aA0 = bA.x, aA1 = bA.y, aA2 = bA.z, aA3 = bA.w;
        float aB0 = bB.x, aB1 = bB.y, aB2 = bB.z, aB3 = bB.w;
#pragma unroll
        for (int k = 0; k < 7; k++) {
            const float xk = xv[k];
            const float4* row = (const float4*)(sW1 + k * 64);
            const float4 wA = row[cgA];
            const float4 wB = row[cgB];
            aA0 += xk * wA.x; aA1 += xk * wA.y; aA2 += xk * wA.z; aA3 += xk * wA.w;
            aB0 += xk * wB.x; aB1 += xk * wB.y; aB2 += xk * wB.z; aB3 += xk * wB.w;
        }
        float4* o = (float4*)(sh1 + nl * HSTR + 8 * s);
        o[rot]     = make_float4(lrelu(aA0), lrelu(aA1), lrelu(aA2), lrelu(aA3));
        o[1 - rot] = make_float4(lrelu(aB0), lrelu(aB1), lrelu(aB2), lrelu(aB3));
    }
    __syncthreads();

    // ---- Stage B: layer 2 ----
    {
        const float4 bA = ((const float4*)sb2)[cgA];
        const float4 bB = ((const float4*)sb2)[cgB];
        float aA0 = bA.x, aA1 = bA.y, aA2 = bA.z, aA3 = bA.w;
        float aB0 = bB.x, aB1 = bB.y, aB2 = bB.z, aB3 = bB.w;
        const float* h1r = sh1 + nl * HSTR;
#pragma unroll
        for (int k = 0; k < 64; k++) {
            const float hk = h1r[k];
            const float4* row = (const float4*)(sW2 + k * 64);
            const float4 wA = row[cgA];
            const float4 wB = row[cgB];
            aA0 += hk * wA.x; aA1 += hk * wA.y; aA2 += hk * wA.z; aA3 += hk * wA.w;
            aB0 += hk * wB.x; aB1 += hk * wB.y; aB2 += hk * wB.z; aB3 += hk * wB.w;
        }
        float4* o = (float4*)(sh2 + nl * HSTR + 8 * s);
        o[rot]     = make_float4(lrelu(aA0), lrelu(aA1), lrelu(aA2), lrelu(aA3));
        o[1 - rot] = make_float4(lrelu(aB0), lrelu(aB1), lrelu(aB2), lrelu(aB3));
    }
    __syncthreads();

    // ---- Stage C: layer 3, dims [4s,4s+4); even/odd accumulator pairs ----
    float f0, f1, f2, f3;
    {
        const float4 b3v = ((const float4*)sb3)[s];
        float e0 = b3v.x, e1 = b3v.y, e2 = b3v.z, e3 = b3v.w;
        float o0 = 0.f, o1 = 0.f, o2 = 0.f, o3 = 0.f;
        const float* h2r = sh2 + nl * HSTR;
#pragma unroll
        for (int j = 0; j < 64; j += 2) {
            const float hj0 = h2r[j];
            const float hj1 = h2r[j + 1];
            const float4 w0 = ((const float4*)sW3)[j * 8 + s];
            const float4 w1 = ((const float4*)sW3)[(j + 1) * 8 + s];
            e0 += hj0 * w0.x; e1 += hj0 * w0.y; e2 += hj0 * w0.z; e3 += hj0 * w0.w;
            o0 += hj1 * w1.x; o1 += hj1 * w1.y; o2 += hj1 * w1.z; o3 += hj1 * w1.w;
        }
        f0 = e0 + o0; f1 = e1 + o1; f2 = e2 + o2; f3 = e3 + o3;
    }
    g_fx4[node * 8 + s] = make_float4(f0, f1, f2, f3);

    // ---- s_j = fx @ Wa[D:]: partial over this lane's 4 dims, 8-lane reduce
    float sj0, sj1, sj2, sj3;
    {
        const float4 w0 = ((const float4*)sWaj)[4 * s + 0];
        const float4 w1 = ((const float4*)sWaj)[4 * s + 1];
        const float4 w2 = ((const float4*)sWaj)[4 * s + 2];
        const float4 w3 = ((const float4*)sWaj)[4 * s + 3];
        sj0 = f0 * w0.x + f1 * w1.x + f2 * w2.x + f3 * w3.x;
        sj1 = f0 * w0.y + f1 * w1.y + f2 * w2.y + f3 * w3.y;
        sj2 = f0 * w0.z + f1 * w1.z + f2 * w2.z + f3 * w3.z;
        sj3 = f0 * w0.w + f1 * w1.w + f2 * w2.w + f3 * w3.w;
    }
#pragma unroll
    for (int o = 1; o < 8; o <<= 1) {
        sj0 += __shfl_xor_sync(0xffffffffu, sj0, o);
        sj1 += __shfl_xor_sync(0xffffffffu, sj1, o);
        sj2 += __shfl_xor_sync(0xffffffffu, sj2, o);
        sj3 += __shfl_xor_sync(0xffffffffu, sj3, o);
    }
    if (s == 0) g_s4[node] = make_float4(sj0, sj1, sj2, sj3);
}

// ---------------------------------------------------------------------------
// Kernel 2: per-batch softmax over j, aggregation m[h][d] (fx tiled through
// shared), projection. 8 blocks x 256 threads.
// ---------------------------------------------------------------------------
__global__ __launch_bounds__(256) void k_att(
    const float* __restrict__ Ws, const float* __restrict__ bs)
{
    const int b = blockIdx.x;
    const int t = threadIdx.x;
    const int w = t >> 5, lane = t & 31;

    __shared__ float ps[4 * 1024];   // exp(s - max), [h][j]
    __shared__ float4 sfx4[256 * 8]; // 256-row fx tile (32 KB)
    __shared__ float red[4 * 8];
    __shared__ float part[256];
    __shared__ float sm[128];
    __shared__ float pr2[128];

    // ---- load s, per-head max ----
    float sv[4][4];
    float lmax[4] = { -1e30f, -1e30f, -1e30f, -1e30f };
#pragma unroll
    for (int jj = 0; jj < 4; jj++) {
        const float4 v = g_s4[b * 1024 + jj * 256 + t];
        sv[jj][0] = v.x; sv[jj][1] = v.y; sv[jj][2] = v.z; sv[jj][3] = v.w;
        lmax[0] = fmaxf(lmax[0], v.x); lmax[1] = fmaxf(lmax[1], v.y);
        lmax[2] = fmaxf(lmax[2], v.z); lmax[3] = fmaxf(lmax[3], v.w);
    }
#pragma unroll
    for (int o = 16; o > 0; o >>= 1)
#pragma unroll
        for (int h = 0; h < 4; h++)
            lmax[h] = fmaxf(lmax[h], __shfl_xor_sync(0xffffffffu, lmax[h], o));
    if (lane == 0)
#pragma unroll
        for (int h = 0; h < 4; h++) red[h * 8 + w] = lmax[h];
    __syncthreads();
    float mx[4];
#pragma unroll
    for (int h = 0; h < 4; h++) {
        float m = red[h * 8];
#pragma unroll
        for (int ww = 1; ww < 8; ww++) m = fmaxf(m, red[h * 8 + ww]);
        mx[h] = m;
    }
    __syncthreads();

    // ---- exp + per-head sum ----
    float lsum[4] = { 0.f, 0.f, 0.f, 0.f };
#pragma unroll
    for (int jj = 0; jj < 4; jj++) {
        const int j = jj * 256 + t;
#pragma unroll
        for (int h = 0; h < 4; h++) {
            const float e = __expf(sv[jj][h] - mx[h]);
            ps[h * 1024 + j] = e;
            lsum[h] += e;
        }
    }
#pragma unroll
    for (int o = 16; o > 0; o >>= 1)
#pragma unroll
        for (int h = 0; h < 4; h++)
            lsum[h] += __shfl_xor_sync(0xffffffffu, lsum[h], o);
    if (lane == 0)
#pragma unroll
        for (int h = 0; h < 4; h++) red[h * 8 + w] = lsum[h];
    __syncthreads();
    float sums[4];
#pragma unroll
    for (int h = 0; h < 4; h++) {
        float s = red[h * 8];
#pragma unroll
        for (int ww = 1; ww < 8; ww++) s += red[h * 8 + ww];
        sums[h] = s;
    }

    // ---- aggregation: m[h][d] = sum_j p[h][j]*fx[j][d], fx tiled via smem.
    const int o = t & 127, half = t >> 7;
    const int h = o >> 5, d = o & 31;
    float a0 = 0.f, a1 = 0.f, a2 = 0.f, a3 = 0.f;
#pragma unroll 1
    for (int tile = 0; tile < 4; tile++) {
        __syncthreads();
        const float4* src = g_fx4 + (b * 1024 + tile * 256) * 8;
        for (int i = t; i < 2048; i += 256) sfx4[i] = src[i];
        __syncthreads();
        const float* pr  = ps + h * 1024 + tile * 256 + half * 128;
        const float* fxp = (const float*)sfx4 + half * 128 * 32 + d;
#pragma unroll 8
        for (int jj = 0; jj < 128; jj += 4) {
            a0 += pr[jj + 0] * fxp[(jj + 0) * 32];
            a1 += pr[jj + 1] * fxp[(jj + 1) * 32];
            a2 += pr[jj + 2] * fxp[(jj + 2) * 32];
            a3 += pr[jj + 3] * fxp[(jj + 3) * 32];
        }
    }
    part[t] = (a0 + a1) + (a2 + a3);
    __syncthreads();
    if (t < 128) sm[t] = (part[t] + part[t + 128]) / sums[h];
    __syncthreads();

    // ---- projection
    if (t < 128) {
        const int kg = t >> 5, dd = t & 31;
        float a = 0.f;
#pragma unroll
        for (int kk = 0; kk < 32; kk++) {
            const int k = kg * 32 + kk;
            a += sm[k] * Ws[k * 32 + dd];
        }
        pr2[t] = a;
    }
    __syncthreads();
    if (t < 32)
        g_o[b * 32 + t] = bs[t] + ((pr2[t] + pr2[t + 32]) + (pr2[t + 64] + pr2[t + 96]));
}

// ---------------------------------------------------------------------------
// Kernel 3: broadcast per-batch rows to the full [B,N,D] output.
// ---------------------------------------------------------------------------
__global__ __launch_bounds__(256) void k_bcast(float4* __restrict__ out)
{
    const int g = blockIdx.x * 256 + threadIdx.x; // float4 index
    const int b = g >> 13;                        // 8192 float4 per batch
    const int d4 = g & 7;
    out[g] = *(const float4*)(g_o + b * 32 + d4 * 4);
}

extern "C" void kernel_launch(void* const* d_in, const int* in_sizes, int n_in,
                              void* d_out, int out_size)
{
    const float* x  = (const float*)d_in[0];
    const float* W1 = (const float*)d_in[1];
    const float* b1 = (const float*)d_in[2];
    const float* W2 = (const float*)d_in[3];
    const float* b2 = (const float*)d_in[4];
    const float* W3 = (const float*)d_in[5];
    const float* b3 = (const float*)d_in[6];
    const float* Wa = (const float*)d_in[7];
    // d_in[8] = ba: cancels in the softmax
    const float* Ws = (const float*)d_in[9];
    const float* bs = (const float*)d_in[10];

    k_mlp<<<256, 256>>>(x, W1, b1, W2, b2, W3, b3, Wa);
    k_att<<<8, 256>>>(Ws, bs);
    k_bcast<<<256, 256>>>((float4*)d_out);
}

// round 8
// speedup vs baseline: 3.9123x; 1.3811x over previous
#include <cuda_runtime.h>

// GATLayer: B=8, N=1024, INP=7, D=32, H=4
// Identity 1: softmax_j(s_i + s_j + ba) == softmax_j(s_j) (s_i, ba const in j)
//   => attention independent of i => output row constant per batch.
// Identity 2: with |s_j| small, softmax needs no max-subtraction in fp32:
//   m[b,h,:] = sum_j e^{s_j[h]} fx[j,:] / sum_j e^{s_j[h]}
//   => the whole aggregation is a per-batch running sum, computed as per-block
//      partials inside the MLP kernel. No N x N work, no big second kernel.

#define BB 8
#define NN 1024
#define DD 32
#define HH 4

// per-block partials: [256 blocks][132] = 128 (e*fx, [h][d]) + 4 (e sums)
__device__ float g_part[256 * 132];
__device__ __align__(16) float g_o[BB * DD]; // per-batch output row [8][32]

static __device__ __forceinline__ float lrelu(float t) {
    return fmaxf(t, 0.2f * t);
}

// ---------------------------------------------------------------------------
// Kernel 1: message MLP + s_j + per-block softmax-numerator partials.
// 256 blocks x 256 threads; 32 nodes/block (all one batch), 8 thr/node (s=t&7).
//  Stage A (L1): lane s computes h1 units [8s,8s+8)  -> smem sh1
//  Stage B (L2): lane s computes h2 units [8s,8s+8)  -> smem sh2
//  Stage C (L3): lane s computes fx dims  [4s,4s+4)
//  Epilogue: s_j (8-lane reduce), e_h = expf(s_h), block-reduce e_h*fx and e_h
//            over the 32 nodes -> one 132-float partial row (plain STG).
// Accumulators are explicit scalars bound to fixed column groups (A<->2s+rot,
// B<->2s+1-rot) so nothing spills; the bank rotation lives only in addresses.
// ---------------------------------------------------------------------------
#define HSTR 68

__global__ __launch_bounds__(256) void k_mlp(
    const float* __restrict__ x,
    const float* __restrict__ W1, const float* __restrict__ b1,
    const float* __restrict__ W2, const float* __restrict__ b2,
    const float* __restrict__ W3, const float* __restrict__ b3,
    const float* __restrict__ Wa)
{
    __shared__ float sW1[7 * 64];
    __shared__ float sW2[64 * 64];
    __shared__ float sW3[64 * 32];
    __shared__ float sWaj[32 * 4];       // Wa rows 32..63, [d][h]
    __shared__ float sb1[64], sb2[64], sb3[32];
    __shared__ float sx[224];            // x for this block's 32 nodes
    __shared__ float sh1[32 * HSTR];     // h1 scratch (bank-skewed rows)
    __shared__ float sh2[32 * HSTR];     // h2 scratch
    __shared__ float stmp[128 * 33];     // e*fx transpose: [(h*32+d)][nl], stride 33
    __shared__ float stz[4 * 33];        // e sums: [h][nl]

    const int t = threadIdx.x;

    // ---- stage weights + x ----
    {
        float4* d2 = (float4*)sW2; const float4* s2 = (const float4*)W2;
#pragma unroll
        for (int i = 0; i < 4; i++) d2[t + i * 256] = s2[t + i * 256];
        float4* d3 = (float4*)sW3; const float4* s3 = (const float4*)W3;
#pragma unroll
        for (int i = 0; i < 2; i++) d3[t + i * 256] = s3[t + i * 256];
        if (t < 112) ((float4*)sW1)[t] = ((const float4*)W1)[t];
        else if (t < 144) ((float4*)sWaj)[t - 112] = ((const float4*)(Wa + 128))[t - 112];
        else if (t < 160) ((float4*)sb1)[t - 144] = ((const float4*)b1)[t - 144];
        else if (t < 176) ((float4*)sb2)[t - 160] = ((const float4*)b2)[t - 160];
        else if (t < 184) ((float4*)sb3)[t - 176] = ((const float4*)b3)[t - 176];
        if (t < 224) sx[t] = __ldg(x + blockIdx.x * 224 + t);
    }
    __syncthreads();

    const int nl = t >> 3;               // node local 0..31
    const int s = t & 7;
    const int rot = s >> 2;              // 0/1
    const int cgA = 2 * s + rot;         // accumulator A's column group (float4 idx)
    const int cgB = 2 * s + 1 - rot;     // accumulator B's column group

    // ---- Stage A: layer 1 ----
    {
        float xv[7];
#pragma unroll
        for (int k = 0; k < 7; k++) xv[k] = sx[nl * 7 + k];

        const float4 bA = ((const float4*)sb1)[cgA];
        const float4 bB = ((const float4*)sb1)[cgB];
        float aA0 = bA.x, aA1 = bA.y, aA2 = bA.z, aA3 = bA.w;
        float aB0 = bB.x, aB1 = bB.y, aB2 = bB.z, aB3 = bB.w;
#pragma unroll
        for (int k = 0; k < 7; k++) {
            const float xk = xv[k];
            const float4* row = (const float4*)(sW1 + k * 64);
            const float4 wA = row[cgA];
            const float4 wB = row[cgB];
            aA0 += xk * wA.x; aA1 += xk * wA.y; aA2 += xk * wA.z; aA3 += xk * wA.w;
            aB0 += xk * wB.x; aB1 += xk * wB.y; aB2 += xk * wB.z; aB3 += xk * wB.w;
        }
        float4* o = (float4*)(sh1 + nl * HSTR + 8 * s);
        o[rot]     = make_float4(lrelu(aA0), lrelu(aA1), lrelu(aA2), lrelu(aA3));
        o[1 - rot] = make_float4(lrelu(aB0), lrelu(aB1), lrelu(aB2), lrelu(aB3));
    }
    __syncthreads();

    // ---- Stage B: layer 2 ----
    {
        const float4 bA = ((const float4*)sb2)[cgA];
        const float4 bB = ((const float4*)sb2)[cgB];
        float aA0 = bA.x, aA1 = bA.y, aA2 = bA.z, aA3 = bA.w;
        float aB0 = bB.x, aB1 = bB.y, aB2 = bB.z, aB3 = bB.w;
        const float* h1r = sh1 + nl * HSTR;
#pragma unroll
        for (int k = 0; k < 64; k++) {
            const float hk = h1r[k];
            const float4* row = (const float4*)(sW2 + k * 64);
            const float4 wA = row[cgA];
            const float4 wB = row[cgB];
            aA0 += hk * wA.x; aA1 += hk * wA.y; aA2 += hk * wA.z; aA3 += hk * wA.w;
            aB0 += hk * wB.x; aB1 += hk * wB.y; aB2 += hk * wB.z; aB3 += hk * wB.w;
        }
        float4* o = (float4*)(sh2 + nl * HSTR + 8 * s);
        o[rot]     = make_float4(lrelu(aA0), lrelu(aA1), lrelu(aA2), lrelu(aA3));
        o[1 - rot] = make_float4(lrelu(aB0), lrelu(aB1), lrelu(aB2), lrelu(aB3));
    }
    __syncthreads();

    // ---- Stage C: layer 3, dims [4s,4s+4); even/odd accumulator pairs ----
    float f0, f1, f2, f3;
    {
        const float4 b3v = ((const float4*)sb3)[s];
        float e0 = b3v.x, e1 = b3v.y, e2 = b3v.z, e3 = b3v.w;
        float o0 = 0.f, o1 = 0.f, o2 = 0.f, o3 = 0.f;
        const float* h2r = sh2 + nl * HSTR;
#pragma unroll
        for (int j = 0; j < 64; j += 2) {
            const float hj0 = h2r[j];
            const float hj1 = h2r[j + 1];
            const float4 w0 = ((const float4*)sW3)[j * 8 + s];
            const float4 w1 = ((const float4*)sW3)[(j + 1) * 8 + s];
            e0 += hj0 * w0.x; e1 += hj0 * w0.y; e2 += hj0 * w0.z; e3 += hj0 * w0.w;
            o0 += hj1 * w1.x; o1 += hj1 * w1.y; o2 += hj1 * w1.z; o3 += hj1 * w1.w;
        }
        f0 = e0 + o0; f1 = e1 + o1; f2 = e2 + o2; f3 = e3 + o3;
    }

    // ---- s_j = fx @ Wa[D:]: partial over this lane's 4 dims, 8-lane all-reduce
    float sj0, sj1, sj2, sj3;
    {
        const float4 w0 = ((const float4*)sWaj)[4 * s + 0];
        const float4 w1 = ((const float4*)sWaj)[4 * s + 1];
        const float4 w2 = ((const float4*)sWaj)[4 * s + 2];
        const float4 w3 = ((const float4*)sWaj)[4 * s + 3];
        sj0 = f0 * w0.x + f1 * w1.x + f2 * w2.x + f3 * w3.x;
        sj1 = f0 * w0.y + f1 * w1.y + f2 * w2.y + f3 * w3.y;
        sj2 = f0 * w0.z + f1 * w1.z + f2 * w2.z + f3 * w3.z;
        sj3 = f0 * w0.w + f1 * w1.w + f2 * w2.w + f3 * w3.w;
    }
#pragma unroll
    for (int o = 1; o < 8; o <<= 1) {
        sj0 += __shfl_xor_sync(0xffffffffu, sj0, o);
        sj1 += __shfl_xor_sync(0xffffffffu, sj1, o);
        sj2 += __shfl_xor_sync(0xffffffffu, sj2, o);
        sj3 += __shfl_xor_sync(0xffffffffu, sj3, o);
    }

    // ---- Epilogue: e_h = exp(s_h); write e_h * f_i into the transpose
    // stmp[(h*32+4s+i)*33 + nl]. Banks: (4s + nl) mod 32 distinct per warp. ----
    {
        const float e0h = __expf(sj0), e1h = __expf(sj1);
        const float e2h = __expf(sj2), e3h = __expf(sj3);
        const int col = 4 * s;
        stmp[(0 * 32 + col + 0) * 33 + nl] = e0h * f0;
        stmp[(0 * 32 + col + 1) * 33 + nl] = e0h * f1;
        stmp[(0 * 32 + col + 2) * 33 + nl] = e0h * f2;
        stmp[(0 * 32 + col + 3) * 33 + nl] = e0h * f3;
        stmp[(1 * 32 + col + 0) * 33 + nl] = e1h * f0;
        stmp[(1 * 32 + col + 1) * 33 + nl] = e1h * f1;
        stmp[(1 * 32 + col + 2) * 33 + nl] = e1h * f2;
        stmp[(1 * 32 + col + 3) * 33 + nl] = e1h * f3;
        stmp[(2 * 32 + col + 0) * 33 + nl] = e2h * f0;
        stmp[(2 * 32 + col + 1) * 33 + nl] = e2h * f1;
        stmp[(2 * 32 + col + 2) * 33 + nl] = e2h * f2;
        stmp[(2 * 32 + col + 3) * 33 + nl] = e2h * f3;
        stmp[(3 * 32 + col + 0) * 33 + nl] = e3h * f0;
        stmp[(3 * 32 + col + 1) * 33 + nl] = e3h * f1;
        stmp[(3 * 32 + col + 2) * 33 + nl] = e3h * f2;
        stmp[(3 * 32 + col + 3) * 33 + nl] = e3h * f3;
        if (s == 0) {
            stz[0 * 33 + nl] = e0h;
            stz[1 * 33 + nl] = e1h;
            stz[2 * 33 + nl] = e2h;
            stz[3 * 33 + nl] = e3h;
        }
    }
    __syncthreads();

    // ---- block reduction over the 32 nodes -> partial row [128 + 4] ----
    if (t < 128) {
        const float* col = stmp + t * 33;
        float a0 = col[0] + col[1], a1 = col[2] + col[3];
        float a2 = col[4] + col[5], a3 = col[6] + col[7];
#pragma unroll
        for (int n = 8; n < 32; n += 8) {
            a0 += col[n + 0] + col[n + 1];
            a1 += col[n + 2] + col[n + 3];
            a2 += col[n + 4] + col[n + 5];
            a3 += col[n + 6] + col[n + 7];
        }
        g_part[blockIdx.x * 132 + t] = (a0 + a1) + (a2 + a3);
    } else if (t < 132) {
        const float* col = stz + (t - 128) * 33;
        float a0 = 0.f, a1 = 0.f, a2 = 0.f, a3 = 0.f;
#pragma unroll
        for (int n = 0; n < 32; n += 4) {
            a0 += col[n + 0]; a1 += col[n + 1];
            a2 += col[n + 2]; a3 += col[n + 3];
        }
        g_part[blockIdx.x * 132 + t] = (a0 + a1) + (a2 + a3);
    }
}

// ---------------------------------------------------------------------------
// Kernel 2: per-batch combine of the 32 partial rows, normalize, projection.
// 8 blocks x 128 threads.
// ---------------------------------------------------------------------------
__global__ __launch_bounds__(128) void k_final(
    const float* __restrict__ Ws, const float* __restrict__ bs)
{
    const int b = blockIdx.x;
    const int t = threadIdx.x;

    __shared__ float sm[128];
    __shared__ float zz[4];
    __shared__ float pr2[128];

    // sum this batch's 32 block-partials for component t
    const float* p = g_part + (b * 32) * 132 + t;
    float a0 = 0.f, a1 = 0.f, a2 = 0.f, a3 = 0.f;
#pragma unroll
    for (int q = 0; q < 32; q += 4) {
        a0 += p[(q + 0) * 132];
        a1 += p[(q + 1) * 132];
        a2 += p[(q + 2) * 132];
        a3 += p[(q + 3) * 132];
    }
    const float msum = (a0 + a1) + (a2 + a3);

    if (t < 4) {
        const float* pz = g_part + (b * 32) * 132 + 128 + t;
        float z0 = 0.f, z1 = 0.f, z2 = 0.f, z3 = 0.f;
#pragma unroll
        for (int q = 0; q < 32; q += 4) {
            z0 += pz[(q + 0) * 132];
            z1 += pz[(q + 1) * 132];
            z2 += pz[(q + 2) * 132];
            z3 += pz[(q + 3) * 132];
        }
        zz[t] = (z0 + z1) + (z2 + z3);
    }
    __syncthreads();

    sm[t] = msum / zz[t >> 5];
    __syncthreads();

    // projection: o[d] = bs[d] + sum_k sm[k] * Ws[k][d], 4-way k split
    const int kg = t >> 5, dd = t & 31;
    float a = 0.f;
#pragma unroll
    for (int kk = 0; kk < 32; kk++) {
        const int k = kg * 32 + kk;
        a += sm[k] * Ws[k * 32 + dd];
    }
    pr2[t] = a;
    __syncthreads();
    if (t < 32)
        g_o[b * 32 + t] = bs[t] + ((pr2[t] + pr2[t + 32]) + (pr2[t + 64] + pr2[t + 96]));
}

// ---------------------------------------------------------------------------
// Kernel 3: broadcast per-batch rows to the full [B,N,D] output.
// ---------------------------------------------------------------------------
__global__ __launch_bounds__(256) void k_bcast(float4* __restrict__ out)
{
    const int g = blockIdx.x * 256 + threadIdx.x; // float4 index
    const int b = g >> 13;                        // 8192 float4 per batch
    const int d4 = g & 7;
    out[g] = *(const float4*)(g_o + b * 32 + d4 * 4);
}

extern "C" void kernel_launch(void* const* d_in, const int* in_sizes, int n_in,
                              void* d_out, int out_size)
{
    const float* x  = (const float*)d_in[0];
    const float* W1 = (const float*)d_in[1];
    const float* b1 = (const float*)d_in[2];
    const float* W2 = (const float*)d_in[3];
    const float* b2 = (const float*)d_in[4];
    const float* W3 = (const float*)d_in[5];
    const float* b3 = (const float*)d_in[6];
    const float* Wa = (const float*)d_in[7];
    // d_in[8] = ba: cancels in the softmax
    const float* Ws = (const float*)d_in[9];
    const float* bs = (const float*)d_in[10];

    k_mlp<<<256, 256>>>(x, W1, b1, W2, b2, W3, b3, Wa);
    k_final<<<8, 128>>>(Ws, bs);
    k_bcast<<<256, 256>>>((float4*)d_out);
}

// round 9
// speedup vs baseline: 5.0108x; 1.2808x over previous
#include <cuda_runtime.h>

// GATLayer: B=8, N=1024, INP=7, D=32, H=4
// Identity 1: softmax_j(s_i + s_j + ba) == softmax_j(s_j) => att independent
//   of i => output row constant per batch.
// Identity 2: |s_j| is small => softmax needs no max subtraction in fp32:
//   m[b,h,:] = sum_j e^{s_j[h]} fx[j,:] / sum_j e^{s_j[h]}
//   => aggregation = per-block partial sums computed inside the MLP kernel.

#define BB 8
#define NN 1024
#define DD 32
#define HH 4

// per-block partials: [128 blocks][132] = 128 (e*fx, [h][d]) + 4 (e sums)
__device__ float g_part[128 * 132];
__device__ __align__(16) float g_o[BB * DD]; // per-batch output row [8][32]

static __device__ __forceinline__ float lrelu(float t) {
    return fmaxf(t, 0.2f * t);
}

// ---------------------------------------------------------------------------
// Kernel 1: message MLP + s_j + per-block softmax-numerator partials.
// 128 blocks x 256 threads; 64 nodes/block (one batch covers 16 blocks),
// 8 threads per NODE PAIR (s = t&7, group g = t>>3 owns nodes g and g+32):
// every weight LDS.128 feeds 16 FFMA (2 nodes x 8), h scalars load as float2.
//  Stage A (L1): lane s computes h1 units [8s,8s+8) for both nodes -> sh1
//  Stage B (L2): lane s computes h2 units [8s,8s+8) for both nodes -> sh2
//  Stage C (L3): lane s computes fx dims  [4s,4s+4) for both nodes
//  Epilogue: s_j (8-lane shfl reduce), e = expf(s), conflict-free smem
//            transpose (stride 65), block-reduce -> one 132-float partial row.
// Accumulators are scalars bound to fixed column groups (A<->2s+rot,
// B<->2s+1-rot, rot=s>>2) so nothing spills; rotation lives only in addresses.
// sh1/sh2 alias the epilogue transpose via a union (barrier separates uses).
// ---------------------------------------------------------------------------
#define HSTR 68
#define TSTR 65

__global__ __launch_bounds__(256) void k_mlp(
    const float* __restrict__ x,
    const float* __restrict__ W1, const float* __restrict__ b1,
    const float* __restrict__ W2, const float* __restrict__ b2,
    const float* __restrict__ W3, const float* __restrict__ b3,
    const float* __restrict__ Wa)
{
    __shared__ float sW1[7 * 64];
    __shared__ float sW2[64 * 64];
    __shared__ float sW3[64 * 32];
    __shared__ float sWaj[32 * 4];       // Wa rows 32..63, [d][h]
    __shared__ float sb1[64], sb2[64], sb3[32];
    __shared__ float sx[448];            // x for this block's 64 nodes
    __shared__ union UU {
        struct { float sh1[64 * HSTR]; float sh2[64 * HSTR]; } a;  // 8704 f
        struct { float stmp[128 * TSTR + TSTR]; float stz[5 * TSTR]; } r; // 8710 f
    } u;

    const int t = threadIdx.x;

    // ---- stage weights + x ----
    {
        float4* d2 = (float4*)sW2; const float4* s2 = (const float4*)W2;
#pragma unroll
        for (int i = 0; i < 4; i++) d2[t + i * 256] = s2[t + i * 256];
        float4* d3 = (float4*)sW3; const float4* s3 = (const float4*)W3;
#pragma unroll
        for (int i = 0; i < 2; i++) d3[t + i * 256] = s3[t + i * 256];
        if (t < 112) {
            ((float4*)sW1)[t] = ((const float4*)W1)[t];
            ((float4*)sx)[t] = ((const float4*)(x + blockIdx.x * 448))[t];
        }
        else if (t < 144) ((float4*)sWaj)[t - 112] = ((const float4*)(Wa + 128))[t - 112];
        else if (t < 160) ((float4*)sb1)[t - 144] = ((const float4*)b1)[t - 144];
        else if (t < 176) ((float4*)sb2)[t - 160] = ((const float4*)b2)[t - 160];
        else if (t < 184) ((float4*)sb3)[t - 176] = ((const float4*)b3)[t - 176];
    }
    __syncthreads();

    const int g = t >> 3;                // node group 0..31 (nodes g, g+32)
    const int s = t & 7;
    const int rot = s >> 2;              // 0/1
    const int cgA = 2 * s + rot;         // accumulator A's column group
    const int cgB = 2 * s + 1 - rot;     // accumulator B's column group

    // ---- Stage A: layer 1 for both nodes ----
    {
        float xv0[7], xv1[7];
#pragma unroll
        for (int k = 0; k < 7; k++) { xv0[k] = sx[g * 7 + k]; xv1[k] = sx[(g + 32) * 7 + k]; }

        const float4 bA = ((const float4*)sb1)[cgA];
        const float4 bB = ((const float4*)sb1)[cgB];
        float nA0 = bA.x, nA1 = bA.y, nA2 = bA.z, nA3 = bA.w;
        float nB0 = bB.x, nB1 = bB.y, nB2 = bB.z, nB3 = bB.w;
        float mA0 = bA.x, mA1 = bA.y, mA2 = bA.z, mA3 = bA.w;
        float mB0 = bB.x, mB1 = bB.y, mB2 = bB.z, mB3 = bB.w;
#pragma unroll
        for (int k = 0; k < 7; k++) {
            const float xk0 = xv0[k], xk1 = xv1[k];
            const float4* row = (const float4*)(sW1 + k * 64);
            const float4 wA = row[cgA];
            const float4 wB = row[cgB];
            nA0 += xk0 * wA.x; nA1 += xk0 * wA.y; nA2 += xk0 * wA.z; nA3 += xk0 * wA.w;
            nB0 += xk0 * wB.x; nB1 += xk0 * wB.y; nB2 += xk0 * wB.z; nB3 += xk0 * wB.w;
            mA0 += xk1 * wA.x; mA1 += xk1 * wA.y; mA2 += xk1 * wA.z; mA3 += xk1 * wA.w;
            mB0 += xk1 * wB.x; mB1 += xk1 * wB.y; mB2 += xk1 * wB.z; mB3 += xk1 * wB.w;
        }
        float4* o0 = (float4*)(u.a.sh1 + g * HSTR + 8 * s);
        float4* o1 = (float4*)(u.a.sh1 + (g + 32) * HSTR + 8 * s);
        o0[rot]     = make_float4(lrelu(nA0), lrelu(nA1), lrelu(nA2), lrelu(nA3));
        o0[1 - rot] = make_float4(lrelu(nB0), lrelu(nB1), lrelu(nB2), lrelu(nB3));
        o1[rot]     = make_float4(lrelu(mA0), lrelu(mA1), lrelu(mA2), lrelu(mA3));
        o1[1 - rot] = make_float4(lrelu(mB0), lrelu(mB1), lrelu(mB2), lrelu(mB3));
    }
    __syncthreads();

    // ---- Stage B: layer 2 for both nodes ----
    {
        const float4 bA = ((const float4*)sb2)[cgA];
        const float4 bB = ((const float4*)sb2)[cgB];
        float nA0 = bA.x, nA1 = bA.y, nA2 = bA.z, nA3 = bA.w;
        float nB0 = bB.x, nB1 = bB.y, nB2 = bB.z, nB3 = bB.w;
        float mA0 = bA.x, mA1 = bA.y, mA2 = bA.z, mA3 = bA.w;
        float mB0 = bB.x, mB1 = bB.y, mB2 = bB.z, mB3 = bB.w;
        const float* h1r0 = u.a.sh1 + g * HSTR;
        const float* h1r1 = u.a.sh1 + (g + 32) * HSTR;
#pragma unroll
        for (int k = 0; k < 64; k += 2) {
            const float2 hk0 = *(const float2*)(h1r0 + k);
            const float2 hk1 = *(const float2*)(h1r1 + k);
            const float4* row0 = (const float4*)(sW2 + k * 64);
            const float4* row1 = (const float4*)(sW2 + (k + 1) * 64);
            {
                const float4 wA = row0[cgA], wB = row0[cgB];
                nA0 += hk0.x * wA.x; nA1 += hk0.x * wA.y; nA2 += hk0.x * wA.z; nA3 += hk0.x * wA.w;
                nB0 += hk0.x * wB.x; nB1 += hk0.x * wB.y; nB2 += hk0.x * wB.z; nB3 += hk0.x * wB.w;
                mA0 += hk1.x * wA.x; mA1 += hk1.x * wA.y; mA2 += hk1.x * wA.z; mA3 += hk1.x * wA.w;
                mB0 += hk1.x * wB.x; mB1 += hk1.x * wB.y; mB2 += hk1.x * wB.z; mB3 += hk1.x * wB.w;
            }
            {
                const float4 wA = row1[cgA], wB = row1[cgB];
                nA0 += hk0.y * wA.x; nA1 += hk0.y * wA.y; nA2 += hk0.y * wA.z; nA3 += hk0.y * wA.w;
                nB0 += hk0.y * wB.x; nB1 += hk0.y * wB.y; nB2 += hk0.y * wB.z; nB3 += hk0.y * wB.w;
                mA0 += hk1.y * wA.x; mA1 += hk1.y * wA.y; mA2 += hk1.y * wA.z; mA3 += hk1.y * wA.w;
                mB0 += hk1.y * wB.x; mB1 += hk1.y * wB.y; mB2 += hk1.y * wB.z; mB3 += hk1.y * wB.w;
            }
        }
        float4* o0 = (float4*)(u.a.sh2 + g * HSTR + 8 * s);
        float4* o1 = (float4*)(u.a.sh2 + (g + 32) * HSTR + 8 * s);
        o0[rot]     = make_float4(lrelu(nA0), lrelu(nA1), lrelu(nA2), lrelu(nA3));
        o0[1 - rot] = make_float4(lrelu(nB0), lrelu(nB1), lrelu(nB2), lrelu(nB3));
        o1[rot]     = make_float4(lrelu(mA0), lrelu(mA1), lrelu(mA2), lrelu(mA3));
        o1[1 - rot] = make_float4(lrelu(mB0), lrelu(mB1), lrelu(mB2), lrelu(mB3));
    }
    __syncthreads();

    // ---- Stage C: layer 3, dims [4s,4s+4) for both nodes ----
    float f0, f1, f2, f3;       // node0 fx
    float q0, q1, q2, q3;       // node1 fx
    {
        const float4 b3v = ((const float4*)sb3)[s];
        float e0 = b3v.x, e1 = b3v.y, e2 = b3v.z, e3 = b3v.w;
        float o0 = 0.f, o1 = 0.f, o2 = 0.f, o3 = 0.f;
        float u0 = b3v.x, u1 = b3v.y, u2 = b3v.z, u3 = b3v.w;
        float v0 = 0.f, v1 = 0.f, v2 = 0.f, v3 = 0.f;
        const float* h2r0 = u.a.sh2 + g * HSTR;
        const float* h2r1 = u.a.sh2 + (g + 32) * HSTR;
#pragma unroll
        for (int j = 0; j < 64; j += 2) {
            const float2 ha = *(const float2*)(h2r0 + j);
            const float2 hb = *(const float2*)(h2r1 + j);
            const float4 w0 = ((const float4*)sW3)[j * 8 + s];
            const float4 w1 = ((const float4*)sW3)[(j + 1) * 8 + s];
            e0 += ha.x * w0.x; e1 += ha.x * w0.y; e2 += ha.x * w0.z; e3 += ha.x * w0.w;
            o0 += ha.y * w1.x; o1 += ha.y * w1.y; o2 += ha.y * w1.z; o3 += ha.y * w1.w;
            u0 += hb.x * w0.x; u1 += hb.x * w0.y; u2 += hb.x * w0.z; u3 += hb.x * w0.w;
            v0 += hb.y * w1.x; v1 += hb.y * w1.y; v2 += hb.y * w1.z; v3 += hb.y * w1.w;
        }
        f0 = e0 + o0; f1 = e1 + o1; f2 = e2 + o2; f3 = e3 + o3;
        q0 = u0 + v0; q1 = u1 + v1; q2 = u2 + v2; q3 = u3 + v3;
    }

    // ---- s_j = fx @ Wa[D:]: partials over lane's 4 dims, 8-lane all-reduce
    float sj0, sj1, sj2, sj3;   // node0
    float tj0, tj1, tj2, tj3;   // node1
    {
        const float4 w0 = ((const float4*)sWaj)[4 * s + 0];
        const float4 w1 = ((const float4*)sWaj)[4 * s + 1];
        const float4 w2 = ((const float4*)sWaj)[4 * s + 2];
        const float4 w3 = ((const float4*)sWaj)[4 * s + 3];
        sj0 = f0 * w0.x + f1 * w1.x + f2 * w2.x + f3 * w3.x;
        sj1 = f0 * w0.y + f1 * w1.y + f2 * w2.y + f3 * w3.y;
        sj2 = f0 * w0.z + f1 * w1.z + f2 * w2.z + f3 * w3.z;
        sj3 = f0 * w0.w + f1 * w1.w + f2 * w2.w + f3 * w3.w;
        tj0 = q0 * w0.x + q1 * w1.x + q2 * w2.x + q3 * w3.x;
        tj1 = q0 * w0.y + q1 * w1.y + q2 * w2.y + q3 * w3.y;
        tj2 = q0 * w0.z + q1 * w1.z + q2 * w2.z + q3 * w3.z;
        tj3 = q0 * w0.w + q1 * w1.w + q2 * w2.w + q3 * w3.w;
    }
#pragma unroll
    for (int o = 1; o < 8; o <<= 1) {
        sj0 += __shfl_xor_sync(0xffffffffu, sj0, o);
        sj1 += __shfl_xor_sync(0xffffffffu, sj1, o);
        sj2 += __shfl_xor_sync(0xffffffffu, sj2, o);
        sj3 += __shfl_xor_sync(0xffffffffu, sj3, o);
        tj0 += __shfl_xor_sync(0xffffffffu, tj0, o);
        tj1 += __shfl_xor_sync(0xffffffffu, tj1, o);
        tj2 += __shfl_xor_sync(0xffffffffu, tj2, o);
        tj3 += __shfl_xor_sync(0xffffffffu, tj3, o);
    }

    // sh1/sh2 are dead, stmp aliases them: barrier before reuse
    __syncthreads();

    // ---- Epilogue: e = exp(s); transpose e*fx into stmp (stride 65:
    // bank = (4s + i + col) % 32, conflict-free; node0 col g, node1 col g+33)
    {
        const float ea0 = __expf(sj0), ea1 = __expf(sj1);
        const float ea2 = __expf(sj2), ea3 = __expf(sj3);
        const float eb0 = __expf(tj0), eb1 = __expf(tj1);
        const float eb2 = __expf(tj2), eb3 = __expf(tj3);
        const int col = 4 * s;
        float* st = u.r.stmp;
#pragma unroll
        for (int h = 0; h < 4; h++) {
            const float eh = (h == 0) ? ea0 : (h == 1) ? ea1 : (h == 2) ? ea2 : ea3;
            st[(h * 32 + col + 0) * TSTR + g] = eh * f0;
            st[(h * 32 + col + 1) * TSTR + g] = eh * f1;
            st[(h * 32 + col + 2) * TSTR + g] = eh * f2;
            st[(h * 32 + col + 3) * TSTR + g] = eh * f3;
        }
#pragma unroll
        for (int h = 0; h < 4; h++) {
            const float eh = (h == 0) ? eb0 : (h == 1) ? eb1 : (h == 2) ? eb2 : eb3;
            st[(h * 32 + col + 0) * TSTR + g + 33] = eh * q0;
            st[(h * 32 + col + 1) * TSTR + g + 33] = eh * q1;
            st[(h * 32 + col + 2) * TSTR + g + 33] = eh * q2;
            st[(h * 32 + col + 3) * TSTR + g + 33] = eh * q3;
        }
        if (s == 0) {
            u.r.stz[0 * TSTR + g] = ea0; u.r.stz[0 * TSTR + g + 33] = eb0;
            u.r.stz[1 * TSTR + g] = ea1; u.r.stz[1 * TSTR + g + 33] = eb1;
            u.r.stz[2 * TSTR + g] = ea2; u.r.stz[2 * TSTR + g + 33] = eb2;
            u.r.stz[3 * TSTR + g] = ea3; u.r.stz[3 * TSTR + g + 33] = eb3;
        }
    }
    __syncthreads();

    // ---- block reduction over 64 nodes -> partial row [128 + 4] ----
    if (t < 128) {
        const float* col = u.r.stmp + t * TSTR;
        float a0 = 0.f, a1 = 0.f, a2 = 0.f, a3 = 0.f;
#pragma unroll
        for (int n = 0; n < 32; n += 4) {
            a0 += col[n + 0]; a1 += col[n + 1];
            a2 += col[n + 2]; a3 += col[n + 3];
        }
#pragma unroll
        for (int n = 33; n < 65; n += 4) {
            a0 += col[n + 0]; a1 += col[n + 1];
            a2 += col[n + 2]; a3 += col[n + 3];
        }
        g_part[blockIdx.x * 132 + t] = (a0 + a1) + (a2 + a3);
    } else if (t < 132) {
        const float* col = u.r.stz + (t - 128) * TSTR;
        float a0 = 0.f, a1 = 0.f, a2 = 0.f, a3 = 0.f;
#pragma unroll
        for (int n = 0; n < 32; n += 4) {
            a0 += col[n + 0]; a1 += col[n + 1];
            a2 += col[n + 2]; a3 += col[n + 3];
        }
#pragma unroll
        for (int n = 33; n < 65; n += 4) {
            a0 += col[n + 0]; a1 += col[n + 1];
            a2 += col[n + 2]; a3 += col[n + 3];
        }
        g_part[blockIdx.x * 132 + t] = (a0 + a1) + (a2 + a3);
    }
}

// ---------------------------------------------------------------------------
// Kernel 2: per-batch combine of the 16 partial rows, normalize, projection.
// 8 blocks x 128 threads.
// ---------------------------------------------------------------------------
__global__ __launch_bounds__(128) void k_final(
    const float* __restrict__ Ws, const float* __restrict__ bs)
{
    const int b = blockIdx.x;
    const int t = threadIdx.x;

    __shared__ float sm[128];
    __shared__ float zz[4];
    __shared__ float pr2[128];

    // sum this batch's 16 block-partials for component t
    const float* p = g_part + (b * 16) * 132 + t;
    float a0 = 0.f, a1 = 0.f, a2 = 0.f, a3 = 0.f;
#pragma unroll
    for (int q = 0; q < 16; q += 4) {
        a0 += p[(q + 0) * 132];
        a1 += p[(q + 1) * 132];
        a2 += p[(q + 2) * 132];
        a3 += p[(q + 3) * 132];
    }
    const float msum = (a0 + a1) + (a2 + a3);

    if (t < 4) {
        const float* pz = g_part + (b * 16) * 132 + 128 + t;
        float z0 = 0.f, z1 = 0.f, z2 = 0.f, z3 = 0.f;
#pragma unroll
        for (int q = 0; q < 16; q += 4) {
            z0 += pz[(q + 0) * 132];
            z1 += pz[(q + 1) * 132];
            z2 += pz[(q + 2) * 132];
            z3 += pz[(q + 3) * 132];
        }
        zz[t] = (z0 + z1) + (z2 + z3);
    }
    __syncthreads();

    sm[t] = msum / zz[t >> 5];
    __syncthreads();

    // projection: o[d] = bs[d] + sum_k sm[k] * Ws[k][d], 4-way k split
    const int kg = t >> 5, dd = t & 31;
    float a = 0.f;
#pragma unroll
    for (int kk = 0; kk < 32; kk++) {
        const int k = kg * 32 + kk;
        a += sm[k] * Ws[k * 32 + dd];
    }
    pr2[t] = a;
    __syncthreads();
    if (t < 32)
        g_o[b * 32 + t] = bs[t] + ((pr2[t] + pr2[t + 32]) + (pr2[t + 64] + pr2[t + 96]));
}

// ---------------------------------------------------------------------------
// Kernel 3: broadcast per-batch rows to the full [B,N,D] output.
// ---------------------------------------------------------------------------
__global__ __launch_bounds__(256) void k_bcast(float4* __restrict__ out)
{
    const int g = blockIdx.x * 256 + threadIdx.x; // float4 index
    const int b = g >> 13;                        // 8192 float4 per batch
    const int d4 = g & 7;
    out[g] = *(const float4*)(g_o + b * 32 + d4 * 4);
}

extern "C" void kernel_launch(void* const* d_in, const int* in_sizes, int n_in,
                              void* d_out, int out_size)
{
    const float* x  = (const float*)d_in[0];
    const float* W1 = (const float*)d_in[1];
    const float* b1 = (const float*)d_in[2];
    const float* W2 = (const float*)d_in[3];
    const float* b2 = (const float*)d_in[4];
    const float* W3 = (const float*)d_in[5];
    const float* b3 = (const float*)d_in[6];
    const float* Wa = (const float*)d_in[7];
    // d_in[8] = ba: cancels in the softmax
    const float* Ws = (const float*)d_in[9];
    const float* bs = (const float*)d_in[10];

    k_mlp<<<128, 256>>>(x, W1, b1, W2, b2, W3, b3, Wa);
    k_final<<<8, 128>>>(Ws, bs);
    k_bcast<<<256, 256>>>((float4*)d_out);
}